// round 15
// baseline (speedup 1.0000x reference)
#include <cuda_runtime.h>
#include <math.h>

typedef unsigned int       u32;
typedef unsigned long long u64;
typedef unsigned short     u16;

#define NB   4
#define NCLS 3
#define FH   256
#define CH   128
#define NIN  128
#define KIN  131
#define PPB  8192
#define PTOT 32768
#define KEYSTRIDE 262144
#define TOPK 8192u

#define PLU    9216               // u32 per plane
#define PLB    36864              // bytes per plane
#define C3CAP  3072

// ---------------- scratch ----------------
__device__ float        g_featT[(size_t)NB*FH*FH*NIN];
__device__ float        g_sem256[NB*NCLS*256*256];
__device__ unsigned int g_keys[NB*KEYSTRIDE];
__device__ unsigned int g_hist2[NB*4096];
__device__ unsigned int g_h2[NB*1024];
__device__ unsigned long long g_cand[(size_t)NB*KEYSTRIDE];
__device__ int          g_bstar[NB];
__device__ int          g_kRem[NB];
__device__ int          g_selCount[NB];
__device__ int          g_candCount[NB];
__device__ int          g_done1[NB];
__device__ int          g_done2[NB];
__device__ int          g_flag[NB];
__device__ int          g_idx[PTOT];
__device__ __align__(16) u32 g_Wf[3*3*PLU];   // [layer][plane][fragment-major]

__device__ __forceinline__ unsigned int fkey(float f) {
    unsigned int u = __float_as_uint(f);
    return (u & 0x80000000u) ? ~u : (u | 0x80000000u);
}
__device__ __forceinline__ u32 pack_bf16x2(float lo_val, float hi_val) {
    u32 r;
    asm("cvt.rn.bf16x2.f32 %0, %1, %2;" : "=r"(r) : "f"(hi_val), "f"(lo_val));
    return r;
}
__device__ __forceinline__ float bf16lo_f(u32 p) { return __uint_as_float(p << 16); }
__device__ __forceinline__ float bf16hi_f(u32 p) { return __uint_as_float(p & 0xFFFF0000u); }

__device__ __forceinline__ void mma16816(float* d, u32 a0, u32 a1, u32 a2, u32 a3, u32 b0, u32 b1) {
    asm volatile("mma.sync.aligned.m16n8k16.row.col.f32.bf16.bf16.f32 {%0,%1,%2,%3}, {%4,%5,%6,%7}, {%8,%9}, {%0,%1,%2,%3};" : "+f"(d[0]), "+f"(d[1]), "+f"(d[2]), "+f"(d[3]) : "r"(a0), "r"(a1), "r"(a2), "r"(a3), "r"(b0), "r"(b1));
}

// X fragment-major address (u32 units) for block-point pt (0..127), k-pair pi (0..71)
__device__ __forceinline__ int xf_addr(int pt, int pi) {
    int w = pt >> 4, r = pt & 15;
    int g = r & 7, rh = r >> 3;
    int ks = pi >> 3, sub = pi & 7;
    int tg = sub & 3, kh = sub >> 2;
    return (((w*9 + ks)*32 + (g << 2) + tg) << 2) + rh + (kh << 1);
}

// ---------------- zero: histograms + counters (main stream) ----------------
__global__ void zero_kernel() {
    int i = blockIdx.x*blockDim.x + threadIdx.x;
    int stride = gridDim.x*blockDim.x;
    for (int j = i; j < NB*4096; j += stride) g_hist2[j] = 0;
    for (int j = i; j < NB*1024; j += stride) g_h2[j] = 0;
    if (i < NB) {
        g_done1[i] = 0; g_done2[i] = 0;
        g_selCount[i] = 0; g_candCount[i] = 0;
        g_flag[i] = 0;
    }
}

// ---------------- W pack (side stream): fragment-major 3-plane ----------------
__global__ void wpack_kernel(const float* __restrict__ w1, const float* __restrict__ w2,
                             const float* __restrict__ w3) {
    int i = blockIdx.x*blockDim.x + threadIdx.x;
    int stride = gridDim.x*blockDim.x;
    for (int j = i; j < 3*PLU; j += stride) {
        int l = j / PLU; int e = j - l*PLU;
        int reg = e & 1;
        int lane = (e >> 1) & 31;
        int nt = (e >> 6) & 15;
        int ks = e >> 10;
        int n  = nt*8 + (lane >> 2);
        int k0 = ks*16 + (lane & 3)*2 + (reg << 3);
        const float* w = (l == 0) ? w1 : ((l == 1) ? w2 : w3);
        float v0 = (k0     < KIN) ? w[n*KIN + k0]     : 0.f;
        float v1 = (k0 + 1 < KIN) ? w[n*KIN + k0 + 1] : 0.f;
        #pragma unroll
        for (int p = 0; p < 3; p++) {
            u32 pk = pack_bf16x2(v0, v1);
            g_Wf[(l*3 + p)*PLU + e] = pk;
            v0 -= bf16lo_f(pk); v1 -= bf16hi_f(pk);
        }
    }
}

// ---------------- features NCHW -> NHWC (side stream) ----------------
__global__ void transpose_kernel(const float* __restrict__ f) {
    __shared__ float tile[32][33];
    int n = blockIdx.z;
    int pix0 = blockIdx.x * 32;
    int c0   = blockIdx.y * 32;
    int tx = threadIdx.x, ty = threadIdx.y;
    #pragma unroll
    for (int i = ty; i < 32; i += 8)
        tile[i][tx] = f[(size_t)(n*NIN + c0 + i)*(FH*FH) + pix0 + tx];
    __syncthreads();
    #pragma unroll
    for (int i = ty; i < 32; i += 8)
        g_featT[(size_t)(n*(FH*FH) + pix0 + i)*NIN + c0 + tx] = tile[tx][i];
}

// ---------------- fused selection: upsample+hist -> resolve -> compact -> exact tail ----------------
__global__ void __launch_bounds__(256)
sel_kernel(const float* __restrict__ in, float* __restrict__ out, int logW, int gen) {
    __shared__ unsigned int sh[4096];
    __shared__ unsigned int wsum[8];
    __shared__ int sh_last, sh_b2, sh_k2, s3cnt;
    int n = blockIdx.y;
    int t = threadIdx.x;
    int lane = t & 31, wrp = t >> 5;
    for (int i = t; i < 4096; i += 256) sh[i] = 0;
    __syncthreads();
    int W = 1 << logW, Hin = W >> 1;
    int HW = W << logW;
    const unsigned int* keys = g_keys + n*KEYSTRIDE;
    unsigned long long* cand = g_cand + (size_t)n*KEYSTRIDE;

    // ---- phase 1: upsample + keys + hist ----
    for (int pix = blockIdx.x*256 + t; pix < HW; pix += gridDim.x*256) {
        int y = pix >> logW;  int x = pix & (W - 1);
        int y0 = (y - 1) >> 1, x0 = (x - 1) >> 1;
        float wy1 = (y & 1) ? 0.25f : 0.75f;
        float wx1 = (x & 1) ? 0.25f : 0.75f;
        int y1 = y0 + 1, x1 = x0 + 1;
        int xa = (x0 < 0) ? 0 : x0;
        int xb = (x1 > Hin-1) ? Hin-1 : x1;
        float v[NCLS];
        #pragma unroll
        for (int c = 0; c < NCLS; c++) {
            const float* p = in + (size_t)(n*NCLS + c)*Hin*Hin;
            float colA, colB;
            if (y0 < 0)            { colA = p[xa];               colB = p[xb]; }
            else if (y1 > Hin - 1) { colA = p[(Hin-1)*Hin + xa]; colB = p[(Hin-1)*Hin + xb]; }
            else {
                colA = (1.f - wy1)*p[y0*Hin + xa] + wy1*p[y1*Hin + xa];
                colB = (1.f - wy1)*p[y0*Hin + xb] + wy1*p[y1*Hin + xb];
            }
            float vv;
            if (x0 < 0)            vv = colA;
            else if (x1 > Hin - 1) vv = colB;
            else                   vv = (1.f - wx1)*colA + wx1*colB;
            v[c] = vv;
            out[(size_t)(n*NCLS + c)*HW + pix] = vv;
        }
        float hi = fmaxf(v[0], v[1]), lo = fminf(v[0], v[1]);
        float m1 = fmaxf(hi, v[2]);
        float m2 = fmaxf(lo, fminf(hi, v[2]));
        unsigned int key = fkey(m2 - m1);
        g_keys[n*KEYSTRIDE + pix] = key;
        atomicAdd(&sh[key >> 20], 1u);
    }
    __syncthreads();
    for (int i = t; i < 4096; i += 256) {
        unsigned int v = sh[i];
        if (v) atomicAdd(&g_hist2[n*4096 + i], v);
    }
    __threadfence();
    if (t == 0) {
        int old = atomicAdd(&g_done1[n], 1);
        sh_last = (old == (int)gridDim.x - 1);
    }
    __syncthreads();

    // ---- last block: resolve 12-bit bucket, publish flag ----
    if (sh_last) {
        unsigned int* gh = g_hist2 + n*4096;
        int base = 4095 - (t << 4);
        unsigned int h[16];
        unsigned int sum = 0;
        #pragma unroll
        for (int j = 0; j < 16; j++) { h[j] = gh[base - j]; sum += h[j]; }
        unsigned int v = sum;
        #pragma unroll
        for (int off = 1; off < 32; off <<= 1) {
            unsigned int u = __shfl_up_sync(0xffffffffu, v, off);
            if (lane >= off) v += u;
        }
        if (lane == 31) wsum[wrp] = v;
        __syncthreads();
        if (wrp == 0 && lane < 8) {
            unsigned int w = wsum[lane];
            #pragma unroll
            for (int off = 1; off < 8; off <<= 1) {
                unsigned int u = __shfl_up_sync(0xffu, w, off);
                if (lane >= off) w += u;
            }
            wsum[lane] = w;
        }
        __syncthreads();
        unsigned int incl = v + (wrp ? wsum[wrp-1] : 0u);
        unsigned int excl = incl - sum;
        if (excl < TOPK && TOPK <= incl) {
            unsigned int c = excl;
            #pragma unroll
            for (int j = 0; j < 16; j++) {
                if (c + h[j] >= TOPK) { g_bstar[n] = base - j; g_kRem[n] = (int)(TOPK - c); break; }
                c += h[j];
            }
        }
        #pragma unroll
        for (int j = 0; j < 16; j++) gh[base - j] = 0;
        if (t == 0) { g_selCount[n] = 0; g_candCount[n] = 0; g_done1[n] = 0; }
        __syncthreads();
        __threadfence();
        if (t == 0) g_flag[n] = gen;
    }

    // ---- all blocks: spin on flag ----
    if (t == 0) {
        volatile int* f = &g_flag[n];
        while (*f < gen) { }
    }
    __syncthreads();
    __threadfence();

    // ---- phase 2: compact (warp-aggregated) + level-2 hist in sh[0..1023] ----
    int bstar = g_bstar[n];
    for (int i = t; i < 1024; i += 256) sh[i] = 0;
    __syncthreads();
    for (int i = blockIdx.x*256 + t; i < HW; i += gridDim.x*256) {
        unsigned int key = keys[i];
        int b = (int)(key >> 20);
        bool isSel  = (b > bstar);
        bool isCand = (b == bstar);
        u32 mS = __ballot_sync(0xffffffffu, isSel);
        u32 mC = __ballot_sync(0xffffffffu, isCand);
        if (isSel) {
            int ldr = __ffs(mS) - 1;
            int base;
            if (lane == ldr) base = atomicAdd(&g_selCount[n], __popc(mS));
            base = __shfl_sync(mS, base, ldr);
            g_idx[n*PPB + base + __popc(mS & ((1u << lane) - 1u))] = i;
        }
        if (isCand) {
            int ldr = __ffs(mC) - 1;
            int base;
            if (lane == ldr) base = atomicAdd(&g_candCount[n], __popc(mC));
            base = __shfl_sync(mC, base, ldr);
            cand[base + __popc(mC & ((1u << lane) - 1u))] =
                (((unsigned long long)(key & 0xFFFFFu)) << 18) | (unsigned int)((~i) & 0x3FFFF);
            atomicAdd(&sh[(key >> 10) & 1023u], 1u);
        }
    }
    __syncthreads();
    for (int i = t; i < 1024; i += 256) {
        if (sh[i]) atomicAdd(&g_h2[n*1024 + i], sh[i]);
    }
    __threadfence();
    if (t == 0) {
        int old = atomicAdd(&g_done2[n], 1);
        sh_last = (old == (int)gridDim.x - 1);
        s3cnt = 0;
    }
    __syncthreads();
    if (!sh_last) return;

    // ---- tail (last block): level-2 scan (4 bins/thread) + emit + exact tie-rank ----
    unsigned int* gh2 = g_h2 + n*1024;
    int base2 = 1023 - (t << 2);
    unsigned int h0 = gh2[base2], h1 = gh2[base2-1], h2v = gh2[base2-2], h3 = gh2[base2-3];
    gh2[base2] = 0; gh2[base2-1] = 0; gh2[base2-2] = 0; gh2[base2-3] = 0;
    unsigned int sum2 = h0 + h1 + h2v + h3;
    unsigned int v2 = sum2;
    #pragma unroll
    for (int off = 1; off < 32; off <<= 1) {
        unsigned int u = __shfl_up_sync(0xffffffffu, v2, off);
        if (lane >= off) v2 += u;
    }
    if (lane == 31) wsum[wrp] = v2;
    __syncthreads();
    if (wrp == 0 && lane < 8) {
        unsigned int w = wsum[lane];
        #pragma unroll
        for (int off = 1; off < 8; off <<= 1) {
            unsigned int u = __shfl_up_sync(0xffu, w, off);
            if (lane >= off) w += u;
        }
        wsum[lane] = w;
    }
    __syncthreads();
    unsigned int need = (unsigned int)g_kRem[n];
    unsigned int incl2 = v2 + (wrp ? wsum[wrp-1] : 0u);
    unsigned int excl2 = incl2 - sum2;
    if (excl2 < need && need <= incl2) {
        unsigned int c = excl2;
        if (c + h0 >= need)      { sh_b2 = base2;     sh_k2 = (int)(need - c); }
        else { c += h0;
        if (c + h1 >= need)      { sh_b2 = base2 - 1; sh_k2 = (int)(need - c); }
        else { c += h1;
        if (c + h2v >= need)     { sh_b2 = base2 - 2; sh_k2 = (int)(need - c); }
        else { c += h2v;           sh_b2 = base2 - 3; sh_k2 = (int)(need - c); } } }
    }
    __syncthreads();
    u32 b2star = (u32)sh_b2;
    int k2 = sh_k2;
    int m = g_candCount[n];
    u32* s3 = sh + 1024;
    for (int i = t; i < m; i += 256) {
        u64 c = cand[i];
        u32 b2 = (u32)(c >> 28) & 1023u;
        if (b2 > b2star) {
            int p = atomicAdd(&g_selCount[n], 1);
            g_idx[n*PPB + p] = (int)((~c) & 0x3FFFF);
        } else if (b2 == b2star) {
            int p = atomicAdd(&s3cnt, 1);
            if (p < C3CAP) s3[p] = (u32)(c & 0xFFFFFFFu);
        }
    }
    __syncthreads();
    int c3 = s3cnt;
    if (c3 <= C3CAP) {
        for (int j = t; j < c3; j += 256) {
            u32 vv = s3[j];
            int r = 0;
            for (int q = 0; q < c3; q++) r += (s3[q] > vv);
            if (r < k2) {
                int p = atomicAdd(&g_selCount[n], 1);
                g_idx[n*PPB + p] = (int)((~vv) & 0x3FFFF);
            }
        }
    } else {
        for (int i = t; i < m; i += 256) {
            u64 c = cand[i];
            if (((u32)(c >> 28) & 1023u) != b2star) continue;
            u32 vv = (u32)(c & 0xFFFFFFFu);
            int r = 0;
            for (int q = 0; q < m; q++) {
                u64 cc = cand[q];
                if (((u32)(cc >> 28) & 1023u) == b2star && (u32)(cc & 0xFFFFFFFu) > vv) r++;
            }
            if (r < k2) {
                int p = atomicAdd(&g_selCount[n], 1);
                g_idx[n*PPB + p] = (int)((~vv) & 0x3FFFF);
            }
        }
    }
    if (t == 0) g_done2[n] = 0;
}

// ---------------- unified MLP: X in smem, W from global (L2-hot), 2x8 warp tiling ----------------
template<int NP>
__global__ void __launch_bounds__(256, 2)
mma_mlp(const float* __restrict__ coarse,
        const float* __restrict__ b1, const float* __restrict__ b2, const float* __restrict__ b3,
        const float* __restrict__ wph, const float* __restrict__ bph,
        float* __restrict__ sem, int HW, int logW) {
    extern __shared__ float dynsm[];
    char* smc = (char*)dynsm;
    u32* XP = (u32*)smc;
    const int MISC = NP*PLB;
    float* bias_s = (float*)(smc + MISC);
    float* hsum   = (float*)(smc + MISC + 512);

    __shared__ int   sx0[128], sy0[128];
    __shared__ float sw0[128], sw1[128], sw2[128], sw3[128];

    int tid = threadIdx.x, lane = tid & 31, wrp = tid >> 5;
    int pBase = blockIdx.x * 128;
    int n = pBase >> 13;

    {
        float4 z = make_float4(0.f, 0.f, 0.f, 0.f);
        float4* xz = (float4*)smc;
        #pragma unroll
        for (int q = 0; q < NP*9; q++) xz[tid + 256*q] = z;
    }
    __syncthreads();
    if (tid < 128) {
        int id = g_idx[pBase + tid];
        int W = 1 << logW;
        float inv = 1.f / (float)W;
        float px = ((float)(id & (W-1)) + 0.5f) * inv;
        float py = ((float)(id >> logW) + 0.5f) * inv;
        float fx = px * 256.f - 0.5f, fy = py * 256.f - 0.5f;
        float fx0 = floorf(fx), fy0 = floorf(fy);
        float wx1 = fx - fx0, wy1 = fy - fy0;
        sx0[tid] = (int)fx0; sy0[tid] = (int)fy0;
        sw0[tid] = (1.f-wx1)*(1.f-wy1);
        sw1[tid] = wx1*(1.f-wy1);
        sw2[tid] = (1.f-wx1)*wy1;
        sw3[tid] = wx1*wy1;
        float cx = px*128.f - 0.5f, cy = py*128.f - 0.5f;
        float cx0f = floorf(cx), cy0f = floorf(cy);
        int x0 = (int)cx0f, y0 = (int)cy0f;
        float cwx = cx - cx0f, cwy = cy - cy0f;
        float cs[NCLS];
        #pragma unroll
        for (int cc = 0; cc < NCLS; cc++) {
            const float* p = coarse + (size_t)(n*NCLS + cc)*CH*CH;
            float acc = 0.f;
            if (x0 >= 0   && y0 >= 0  ) acc += (1.f-cwx)*(1.f-cwy)*p[y0*CH + x0];
            if (x0+1 < CH && y0 >= 0  ) acc += cwx*(1.f-cwy)*p[y0*CH + x0+1];
            if (x0 >= 0   && y0+1 < CH) acc += (1.f-cwx)*cwy*p[(y0+1)*CH + x0];
            if (x0+1 < CH && y0+1 < CH) acc += cwx*cwy*p[(y0+1)*CH + x0+1];
            cs[cc] = acc;
        }
        int ad64 = xf_addr(tid, 64);
        int ad65 = xf_addr(tid, 65);
        float r0 = cs[0], r1 = cs[1], r2 = cs[2], r3 = 0.f;
        #pragma unroll
        for (int p = 0; p < NP; p++) {
            u32 pkA = pack_bf16x2(r0, r1);
            u32 pkB = pack_bf16x2(r2, r3);
            XP[p*PLU + ad64] = pkA;
            XP[p*PLU + ad65] = pkB;
            r0 -= bf16lo_f(pkA); r1 -= bf16hi_f(pkA);
            r2 -= bf16lo_f(pkB); r3 -= bf16hi_f(pkB);
        }
        #pragma unroll
        for (int c = 0; c < NCLS; c++)
            hsum[c*128 + tid] = __ldg(&wph[c*KIN + 128])*cs[0] + __ldg(&wph[c*KIN + 129])*cs[1]
                              + __ldg(&wph[c*KIN + 130])*cs[2] + __ldg(&bph[c]);
    }
    __syncthreads();

    const float* fbase = g_featT + (size_t)n*FH*FH*NIN;
    int ch0 = lane << 2;
    #pragma unroll 4
    for (int it = 0; it < 16; it++) {
        int pt = wrp + it*8;
        int x0 = sx0[pt], y0 = sy0[pt];
        bool xv0 = (x0 >= 0), xv1 = (x0+1 < FH), yv0 = (y0 >= 0), yv1 = (y0+1 < FH);
        float a0 = 0.f, a1 = 0.f, a2 = 0.f, a3 = 0.f;
        if (xv0 && yv0) { float w = sw0[pt]; float4 v = *(const float4*)(fbase + (size_t)((y0  )*FH + x0  )*NIN + ch0);
                          a0 += w*v.x; a1 += w*v.y; a2 += w*v.z; a3 += w*v.w; }
        if (xv1 && yv0) { float w = sw1[pt]; float4 v = *(const float4*)(fbase + (size_t)((y0  )*FH + x0+1)*NIN + ch0);
                          a0 += w*v.x; a1 += w*v.y; a2 += w*v.z; a3 += w*v.w; }
        if (xv0 && yv1) { float w = sw2[pt]; float4 v = *(const float4*)(fbase + (size_t)((y0+1)*FH + x0  )*NIN + ch0);
                          a0 += w*v.x; a1 += w*v.y; a2 += w*v.z; a3 += w*v.w; }
        if (xv1 && yv1) { float w = sw3[pt]; float4 v = *(const float4*)(fbase + (size_t)((y0+1)*FH + x0+1)*NIN + ch0);
                          a0 += w*v.x; a1 += w*v.y; a2 += w*v.z; a3 += w*v.w; }
        int ad0 = xf_addr(pt, (lane << 1));
        int ad1 = xf_addr(pt, (lane << 1) + 1);
        float r0 = a0, r1 = a1, r2 = a2, r3 = a3;
        #pragma unroll
        for (int p = 0; p < NP; p++) {
            u32 pkA = pack_bf16x2(r0, r1);
            u32 pkB = pack_bf16x2(r2, r3);
            XP[p*PLU + ad0] = pkA;
            XP[p*PLU + ad1] = pkB;
            r0 -= bf16lo_f(pkA); r1 -= bf16hi_f(pkA);
            r2 -= bf16lo_f(pkB); r3 -= bf16hi_f(pkB);
        }
    }
    __syncthreads();

    const int NPROD = (NP == 2) ? 3 : 6;
    const int PA[6] = {0, 0, 1, 1, 0, 2};
    const int PB[6] = {0, 1, 0, 1, 2, 0};

    int g = lane >> 2;
    int tig = lane & 3;
    int wm = wrp & 3;
    int wn = wrp >> 2;

    for (int l = 0; l < 3; l++) {
        const float* Bp = (l == 0) ? b1 : ((l == 1) ? b2 : b3);
        if (tid < 128) bias_s[tid] = __ldg(&Bp[tid]);
        __syncthreads();
        const u32* Wg = g_Wf + (size_t)l*3*PLU;

        float acc[2][8][4];
        #pragma unroll
        for (int mi = 0; mi < 2; mi++)
            #pragma unroll
            for (int j = 0; j < 8; j++) {
                acc[mi][j][0] = 0.f; acc[mi][j][1] = 0.f;
                acc[mi][j][2] = 0.f; acc[mi][j][3] = 0.f;
            }
        for (int ks = 0; ks < 9; ks++) {
            uint4 afA[NP], afB[NP];
            #pragma unroll
            for (int p = 0; p < NP; p++) {
                afA[p] = *(const uint4*)(XP + p*PLU + ((((2*wm  )*9 + ks)*32 + lane) << 2));
                afB[p] = *(const uint4*)(XP + p*PLU + ((((2*wm+1)*9 + ks)*32 + lane) << 2));
            }
            #pragma unroll
            for (int j = 0; j < 8; j++) {
                int nt = wn*8 + j;
                int boff = (((ks*16 + nt)*32 + lane) << 1);
                uint2 bfr[NP];
                #pragma unroll
                for (int p = 0; p < NP; p++)
                    bfr[p] = __ldg((const uint2*)(Wg + p*PLU + boff));
                #pragma unroll
                for (int q = 0; q < NPROD; q++) {
                    mma16816(acc[0][j], afA[PA[q]].x, afA[PA[q]].y, afA[PA[q]].z, afA[PA[q]].w,
                             bfr[PB[q]].x, bfr[PB[q]].y);
                    mma16816(acc[1][j], afB[PA[q]].x, afB[PA[q]].y, afB[PA[q]].z, afB[PA[q]].w,
                             bfr[PB[q]].x, bfr[PB[q]].y);
                }
            }
        }
        __syncthreads();

        #pragma unroll
        for (int mi = 0; mi < 2; mi++) {
            int mt = 2*wm + mi;
            #pragma unroll
            for (int j = 0; j < 8; j++) {
                int nt = wn*8 + j;
                int col = nt*8 + (tig << 1);
                float bA = bias_s[col], bB = bias_s[col + 1];
                float v0 = fmaxf(acc[mi][j][0] + bA, 0.f);
                float v1 = fmaxf(acc[mi][j][1] + bB, 0.f);
                float v2 = fmaxf(acc[mi][j][2] + bA, 0.f);
                float v3 = fmaxf(acc[mi][j][3] + bB, 0.f);
                int pi = nt*4 + tig;
                int adA = xf_addr(mt*16 + g, pi);
                float r0 = v0, r1 = v1, r2 = v2, r3 = v3;
                #pragma unroll
                for (int p = 0; p < NP; p++) {
                    u32 pkA = pack_bf16x2(r0, r1);
                    u32 pkB = pack_bf16x2(r2, r3);
                    *(uint2*)(XP + p*PLU + adA) = make_uint2(pkA, pkB);
                    r0 -= bf16lo_f(pkA); r1 -= bf16hi_f(pkA);
                    r2 -= bf16lo_f(pkB); r3 -= bf16hi_f(pkB);
                }
            }
        }
        __syncthreads();
    }

    if (tid < 128) {
        float s0 = 0.f, s1 = 0.f, s2 = 0.f;
        #pragma unroll 8
        for (int kp = 0; kp < 64; kp++) {
            int ad = xf_addr(tid, kp);
            float x0 = 0.f, x1 = 0.f;
            #pragma unroll
            for (int p = 0; p < NP; p++) {
                u32 v = XP[p*PLU + ad];
                x0 += bf16lo_f(v); x1 += bf16hi_f(v);
            }
            int k = kp << 1;
            s0 += __ldg(&wph[k])*x0 + __ldg(&wph[k+1])*x1;
            s1 += __ldg(&wph[KIN + k])*x0 + __ldg(&wph[KIN + k + 1])*x1;
            s2 += __ldg(&wph[2*KIN + k])*x0 + __ldg(&wph[2*KIN + k + 1])*x1;
        }
        int id = g_idx[pBase + tid];
        sem[(size_t)(n*NCLS + 0)*HW + id] = hsum[tid] + s0;
        sem[(size_t)(n*NCLS + 1)*HW + id] = hsum[128 + tid] + s1;
        sem[(size_t)(n*NCLS + 2)*HW + id] = hsum[256 + tid] + s2;
    }
}

// ---------------- launch ----------------
extern "C" void kernel_launch(void* const* d_in, const int* in_sizes, int n_in,
                              void* d_out, int out_size) {
    const float* coarse = (const float*)d_in[0];
    const float* feat   = (const float*)d_in[1];
    const float* w1 = (const float*)d_in[2];
    const float* b1 = (const float*)d_in[3];
    const float* w2 = (const float*)d_in[4];
    const float* b2 = (const float*)d_in[5];
    const float* w3 = (const float*)d_in[6];
    const float* b3 = (const float*)d_in[7];
    const float* wp = (const float*)d_in[8];
    const float* bp = (const float*)d_in[9];
    float* out = (float*)d_out;

    float* sem256;
    cudaGetSymbolAddress((void**)&sem256, g_sem256);

    static cudaStream_t sSide = nullptr;
    static cudaEvent_t evFork = nullptr, evJoin = nullptr;
    if (sSide == nullptr) {
        cudaStreamCreateWithFlags(&sSide, cudaStreamNonBlocking);
        cudaEventCreateWithFlags(&evFork, cudaEventDisableTiming);
        cudaEventCreateWithFlags(&evJoin, cudaEventDisableTiming);
    }

    const int SM3 = 3*PLB + 2048;   // 112,640 B -> 2 blocks/SM
    const int SM2 = 2*PLB + 2048;   //  75,776 B
    cudaFuncSetAttribute(mma_mlp<3>, cudaFuncAttributeMaxDynamicSharedMemorySize, SM3);
    cudaFuncSetAttribute(mma_mlp<2>, cudaFuncAttributeMaxDynamicSharedMemorySize, SM2);

    // side stream: W pack + feature transpose (independent of main-stream selection)
    cudaEventRecord(evFork, 0);
    cudaStreamWaitEvent(sSide, evFork, 0);
    wpack_kernel<<<128, 256, 0, sSide>>>(w1, w2, w3);
    transpose_kernel<<<dim3(2048, 4, 4), dim3(32, 8), 0, sSide>>>(feat);
    cudaEventRecord(evJoin, sSide);

    zero_kernel<<<64, 256>>>();

    for (int step = 0; step < 2; step++) {
        int logW = (step == 0) ? 8 : 9;
        int HW   = 1 << (2*logW);
        const float* semIn = (step == 0) ? coarse : sem256;
        float* semOut      = (step == 0) ? sem256 : out;

        sel_kernel<<<dim3(64, NB), 256>>>(semIn, semOut, logW, step + 1);

        if (step == 0) {
            cudaStreamWaitEvent(0, evJoin, 0);
            mma_mlp<3><<<PTOT/128, 256, SM3>>>(coarse, b1, b2, b3, wp, bp, semOut, HW, logW);
        } else {
            mma_mlp<2><<<PTOT/128, 256, SM2>>>(coarse, b1, b2, b3, wp, bp, semOut, HW, logW);
        }
    }
}

// round 16
// speedup vs baseline: 1.0385x; 1.0385x over previous
#include <cuda_runtime.h>
#include <math.h>

typedef unsigned int       u32;
typedef unsigned long long u64;
typedef unsigned short     u16;

#define NB   4
#define NCLS 3
#define FH   256
#define CH   128
#define NIN  128
#define KIN  131
#define PPB  8192
#define PTOT 32768
#define KEYSTRIDE 262144
#define TOPK 8192u

#define PLU    9216               // u32 per plane
#define PLB    36864              // bytes per plane
#define C3CAP  2048

// ---------------- scratch ----------------
__device__ float        g_featT[(size_t)NB*FH*FH*NIN];
__device__ float        g_sem256[NB*NCLS*256*256];
__device__ unsigned int g_keys[NB*KEYSTRIDE];
__device__ unsigned int g_hist2[NB*4096];
__device__ unsigned int g_h2[NB*1024];
__device__ unsigned long long g_cand[(size_t)NB*KEYSTRIDE];
__device__ int          g_bstar[NB];
__device__ int          g_kRem[NB];
__device__ int          g_selCount[NB];
__device__ int          g_candCount[NB];
__device__ int          g_done1[NB];
__device__ int          g_done2[NB];
__device__ int          g_idx[PTOT];
__device__ __align__(16) u32 g_Wf[3*3*PLU];   // [layer][plane][fragment-major]

__device__ __forceinline__ unsigned int fkey(float f) {
    unsigned int u = __float_as_uint(f);
    return (u & 0x80000000u) ? ~u : (u | 0x80000000u);
}
__device__ __forceinline__ u32 pack_bf16x2(float lo_val, float hi_val) {
    u32 r;
    asm("cvt.rn.bf16x2.f32 %0, %1, %2;" : "=r"(r) : "f"(hi_val), "f"(lo_val));
    return r;
}
__device__ __forceinline__ float bf16lo_f(u32 p) { return __uint_as_float(p << 16); }
__device__ __forceinline__ float bf16hi_f(u32 p) { return __uint_as_float(p & 0xFFFF0000u); }

__device__ __forceinline__ void mma16816(float* d, u32 a0, u32 a1, u32 a2, u32 a3, u32 b0, u32 b1) {
    asm volatile("mma.sync.aligned.m16n8k16.row.col.f32.bf16.bf16.f32 {%0,%1,%2,%3}, {%4,%5,%6,%7}, {%8,%9}, {%0,%1,%2,%3};" : "+f"(d[0]), "+f"(d[1]), "+f"(d[2]), "+f"(d[3]) : "r"(a0), "r"(a1), "r"(a2), "r"(a3), "r"(b0), "r"(b1));
}

// X fragment-major address (u32 units) for block-point pt (0..127), k-pair pi (0..71)
__device__ __forceinline__ int xf_addr(int pt, int pi) {
    int w = pt >> 4, r = pt & 15;
    int g = r & 7, rh = r >> 3;
    int ks = pi >> 3, sub = pi & 7;
    int tg = sub & 3, kh = sub >> 2;
    return (((w*9 + ks)*32 + (g << 2) + tg) << 2) + rh + (kh << 1);
}

// ---------------- zero: histograms + counters (main stream, tiny) ----------------
__global__ void zero_kernel() {
    int i = blockIdx.x*blockDim.x + threadIdx.x;
    int stride = gridDim.x*blockDim.x;
    for (int j = i; j < NB*4096; j += stride) g_hist2[j] = 0;
    for (int j = i; j < NB*1024; j += stride) g_h2[j] = 0;
    if (i < NB) {
        g_done1[i] = 0; g_done2[i] = 0;
        g_selCount[i] = 0; g_candCount[i] = 0;
    }
}

// ---------------- W pack (side stream): fragment-major 3-plane ----------------
__global__ void wpack_kernel(const float* __restrict__ w1, const float* __restrict__ w2,
                             const float* __restrict__ w3) {
    int i = blockIdx.x*blockDim.x + threadIdx.x;
    int stride = gridDim.x*blockDim.x;
    for (int j = i; j < 3*PLU; j += stride) {
        int l = j / PLU; int e = j - l*PLU;
        int reg = e & 1;
        int lane = (e >> 1) & 31;
        int nt = (e >> 6) & 15;
        int ks = e >> 10;
        int n  = nt*8 + (lane >> 2);
        int k0 = ks*16 + (lane & 3)*2 + (reg << 3);
        const float* w = (l == 0) ? w1 : ((l == 1) ? w2 : w3);
        float v0 = (k0     < KIN) ? w[n*KIN + k0]     : 0.f;
        float v1 = (k0 + 1 < KIN) ? w[n*KIN + k0 + 1] : 0.f;
        #pragma unroll
        for (int p = 0; p < 3; p++) {
            u32 pk = pack_bf16x2(v0, v1);
            g_Wf[(l*3 + p)*PLU + e] = pk;
            v0 -= bf16lo_f(pk); v1 -= bf16hi_f(pk);
        }
    }
}

// ---------------- features NCHW -> NHWC (side stream) ----------------
__global__ void transpose_kernel(const float* __restrict__ f) {
    __shared__ float tile[32][33];
    int n = blockIdx.z;
    int pix0 = blockIdx.x * 32;
    int c0   = blockIdx.y * 32;
    int tx = threadIdx.x, ty = threadIdx.y;
    #pragma unroll
    for (int i = ty; i < 32; i += 8)
        tile[i][tx] = f[(size_t)(n*NIN + c0 + i)*(FH*FH) + pix0 + tx];
    __syncthreads();
    #pragma unroll
    for (int i = ty; i < 32; i += 8)
        g_featT[(size_t)(n*(FH*FH) + pix0 + i)*NIN + c0 + tx] = tile[tx][i];
}

// ---------------- K1: upsample + keys + hist; last block resolves ----------------
__global__ void upsample_sel(const float* __restrict__ in, float* __restrict__ out, int logW) {
    __shared__ unsigned int sh[4096];
    __shared__ unsigned int wsum[8];
    __shared__ int sh_last;
    int n = blockIdx.y;
    int t = threadIdx.x;
    int lane = t & 31, wrp = t >> 5;
    for (int i = t; i < 4096; i += 256) sh[i] = 0;
    __syncthreads();
    int W = 1 << logW, Hin = W >> 1;
    int HW = W << logW;
    for (int pix = blockIdx.x*256 + t; pix < HW; pix += gridDim.x*256) {
        int y = pix >> logW;  int x = pix & (W - 1);
        int y0 = (y - 1) >> 1, x0 = (x - 1) >> 1;
        float wy1 = (y & 1) ? 0.25f : 0.75f;
        float wx1 = (x & 1) ? 0.25f : 0.75f;
        int y1 = y0 + 1, x1 = x0 + 1;
        int xa = (x0 < 0) ? 0 : x0;
        int xb = (x1 > Hin-1) ? Hin-1 : x1;
        float v[NCLS];
        #pragma unroll
        for (int c = 0; c < NCLS; c++) {
            const float* p = in + (size_t)(n*NCLS + c)*Hin*Hin;
            float colA, colB;
            if (y0 < 0)            { colA = p[xa];               colB = p[xb]; }
            else if (y1 > Hin - 1) { colA = p[(Hin-1)*Hin + xa]; colB = p[(Hin-1)*Hin + xb]; }
            else {
                colA = (1.f - wy1)*p[y0*Hin + xa] + wy1*p[y1*Hin + xa];
                colB = (1.f - wy1)*p[y0*Hin + xb] + wy1*p[y1*Hin + xb];
            }
            float vv;
            if (x0 < 0)            vv = colA;
            else if (x1 > Hin - 1) vv = colB;
            else                   vv = (1.f - wx1)*colA + wx1*colB;
            v[c] = vv;
            out[(size_t)(n*NCLS + c)*HW + pix] = vv;
        }
        float hi = fmaxf(v[0], v[1]), lo = fminf(v[0], v[1]);
        float m1 = fmaxf(hi, v[2]);
        float m2 = fmaxf(lo, fminf(hi, v[2]));
        unsigned int key = fkey(m2 - m1);
        g_keys[n*KEYSTRIDE + pix] = key;
        atomicAdd(&sh[key >> 20], 1u);
    }
    __syncthreads();
    for (int i = t; i < 4096; i += 256) {
        unsigned int v = sh[i];
        if (v) atomicAdd(&g_hist2[n*4096 + i], v);
    }
    __threadfence();
    if (t == 0) {
        int old = atomicAdd(&g_done1[n], 1);
        sh_last = (old == (int)gridDim.x - 1);
    }
    __syncthreads();
    if (!sh_last) return;
    unsigned int* gh = g_hist2 + n*4096;
    int base = 4095 - (t << 4);
    unsigned int h[16];
    unsigned int sum = 0;
    #pragma unroll
    for (int j = 0; j < 16; j++) { h[j] = gh[base - j]; sum += h[j]; }
    unsigned int v = sum;
    #pragma unroll
    for (int off = 1; off < 32; off <<= 1) {
        unsigned int u = __shfl_up_sync(0xffffffffu, v, off);
        if (lane >= off) v += u;
    }
    if (lane == 31) wsum[wrp] = v;
    __syncthreads();
    if (wrp == 0 && lane < 8) {
        unsigned int w = wsum[lane];
        #pragma unroll
        for (int off = 1; off < 8; off <<= 1) {
            unsigned int u = __shfl_up_sync(0xffu, w, off);
            if (lane >= off) w += u;
        }
        wsum[lane] = w;
    }
    __syncthreads();
    unsigned int incl = v + (wrp ? wsum[wrp-1] : 0u);
    unsigned int excl = incl - sum;
    if (excl < TOPK && TOPK <= incl) {
        unsigned int c = excl;
        #pragma unroll
        for (int j = 0; j < 16; j++) {
            if (c + h[j] >= TOPK) { g_bstar[n] = base - j; g_kRem[n] = (int)(TOPK - c); break; }
            c += h[j];
        }
    }
    #pragma unroll
    for (int j = 0; j < 16; j++) gh[base - j] = 0;
    if (t == 0) { g_selCount[n] = 0; g_candCount[n] = 0; g_done1[n] = 0; }
}

// ---------------- K2: compact + level-2 hist; last block: scan + exact tie-rank ----------------
__global__ void __launch_bounds__(1024)
compact_sel(int HW) {
    __shared__ unsigned int h2s[1024];
    __shared__ unsigned int wsum[32];
    __shared__ int sh_last, sh_b2, sh_k2, s3cnt;
    __shared__ u32 s3[C3CAP];
    int n = blockIdx.y;
    int t = threadIdx.x;
    int lane = t & 31, wrp = t >> 5;
    int bstar = g_bstar[n];
    const unsigned int* keys = g_keys + n*KEYSTRIDE;
    unsigned long long* cand = g_cand + (size_t)n*KEYSTRIDE;
    h2s[t] = 0;
    __syncthreads();
    for (int i = blockIdx.x*1024 + t; i < HW; i += gridDim.x*1024) {
        unsigned int key = keys[i];
        int b = (int)(key >> 20);
        bool isSel  = (b > bstar);
        bool isCand = (b == bstar);
        u32 mS = __ballot_sync(0xffffffffu, isSel);
        u32 mC = __ballot_sync(0xffffffffu, isCand);
        if (isSel) {
            int ldr = __ffs(mS) - 1;
            int base;
            if (lane == ldr) base = atomicAdd(&g_selCount[n], __popc(mS));
            base = __shfl_sync(mS, base, ldr);
            g_idx[n*PPB + base + __popc(mS & ((1u << lane) - 1u))] = i;
        }
        if (isCand) {
            int ldr = __ffs(mC) - 1;
            int base;
            if (lane == ldr) base = atomicAdd(&g_candCount[n], __popc(mC));
            base = __shfl_sync(mC, base, ldr);
            cand[base + __popc(mC & ((1u << lane) - 1u))] =
                (((unsigned long long)(key & 0xFFFFFu)) << 18) | (unsigned int)((~i) & 0x3FFFF);
            atomicAdd(&h2s[(key >> 10) & 1023u], 1u);
        }
    }
    __syncthreads();
    if (h2s[t]) atomicAdd(&g_h2[n*1024 + t], h2s[t]);
    __threadfence();
    if (t == 0) {
        int old = atomicAdd(&g_done2[n], 1);
        sh_last = (old == (int)gridDim.x - 1);
        s3cnt = 0;
    }
    __syncthreads();
    if (!sh_last) return;
    unsigned int val = g_h2[n*1024 + (1023 - t)];
    g_h2[n*1024 + (1023 - t)] = 0;
    unsigned int v = val;
    #pragma unroll
    for (int off = 1; off < 32; off <<= 1) {
        unsigned int u = __shfl_up_sync(0xffffffffu, v, off);
        if (lane >= off) v += u;
    }
    if (lane == 31) wsum[wrp] = v;
    __syncthreads();
    if (wrp == 0) {
        unsigned int w = wsum[lane];
        #pragma unroll
        for (int off = 1; off < 32; off <<= 1) {
            unsigned int u = __shfl_up_sync(0xffffffffu, w, off);
            if (lane >= off) w += u;
        }
        wsum[lane] = w;
    }
    __syncthreads();
    unsigned int need = (unsigned int)g_kRem[n];
    unsigned int incl = v + (wrp ? wsum[wrp-1] : 0u);
    unsigned int excl = incl - val;
    if (excl < need && need <= incl) { sh_b2 = 1023 - t; sh_k2 = (int)(need - excl); }
    __syncthreads();
    u32 b2star = (u32)sh_b2;
    int k2 = sh_k2;
    int m = g_candCount[n];
    for (int i = t; i < m; i += 1024) {
        u64 c = cand[i];
        u32 b2 = (u32)(c >> 28) & 1023u;
        if (b2 > b2star) {
            int p = atomicAdd(&g_selCount[n], 1);
            g_idx[n*PPB + p] = (int)((~c) & 0x3FFFF);
        } else if (b2 == b2star) {
            int p = atomicAdd(&s3cnt, 1);
            if (p < C3CAP) s3[p] = (u32)(c & 0xFFFFFFFu);
        }
    }
    __syncthreads();
    int c3 = s3cnt;
    if (c3 <= C3CAP) {
        for (int j = t; j < c3; j += 1024) {
            u32 vv = s3[j];
            int r = 0;
            for (int q = 0; q < c3; q++) r += (s3[q] > vv);
            if (r < k2) {
                int p = atomicAdd(&g_selCount[n], 1);
                g_idx[n*PPB + p] = (int)((~vv) & 0x3FFFF);
            }
        }
    } else {
        for (int i = t; i < m; i += 1024) {
            u64 c = cand[i];
            if (((u32)(c >> 28) & 1023u) != b2star) continue;
            u32 vv = (u32)(c & 0xFFFFFFFu);
            int r = 0;
            for (int q = 0; q < m; q++) {
                u64 cc = cand[q];
                if (((u32)(cc >> 28) & 1023u) == b2star && (u32)(cc & 0xFFFFFFFu) > vv) r++;
            }
            if (r < k2) {
                int p = atomicAdd(&g_selCount[n], 1);
                g_idx[n*PPB + p] = (int)((~vv) & 0x3FFFF);
            }
        }
    }
    if (t == 0) g_done2[n] = 0;
}

// ---------------- unified MLP: X in smem, W from global (L2-hot), 2x8 warp tiling ----------------
template<int NP>
__global__ void __launch_bounds__(256, 2)
mma_mlp(const float* __restrict__ coarse,
        const float* __restrict__ b1, const float* __restrict__ b2, const float* __restrict__ b3,
        const float* __restrict__ wph, const float* __restrict__ bph,
        float* __restrict__ sem, int HW, int logW) {
    extern __shared__ float dynsm[];
    char* smc = (char*)dynsm;
    u32* XP = (u32*)smc;
    const int MISC = NP*PLB;
    float* bias_s = (float*)(smc + MISC);
    float* hsum   = (float*)(smc + MISC + 512);

    __shared__ int   sx0[128], sy0[128];
    __shared__ float sw0[128], sw1[128], sw2[128], sw3[128];

    int tid = threadIdx.x, lane = tid & 31, wrp = tid >> 5;
    int pBase = blockIdx.x * 128;
    int n = pBase >> 13;

    {
        float4 z = make_float4(0.f, 0.f, 0.f, 0.f);
        float4* xz = (float4*)smc;
        #pragma unroll
        for (int q = 0; q < NP*9; q++) xz[tid + 256*q] = z;
    }
    __syncthreads();
    if (tid < 128) {
        int id = g_idx[pBase + tid];
        int W = 1 << logW;
        float inv = 1.f / (float)W;
        float px = ((float)(id & (W-1)) + 0.5f) * inv;
        float py = ((float)(id >> logW) + 0.5f) * inv;
        float fx = px * 256.f - 0.5f, fy = py * 256.f - 0.5f;
        float fx0 = floorf(fx), fy0 = floorf(fy);
        float wx1 = fx - fx0, wy1 = fy - fy0;
        sx0[tid] = (int)fx0; sy0[tid] = (int)fy0;
        sw0[tid] = (1.f-wx1)*(1.f-wy1);
        sw1[tid] = wx1*(1.f-wy1);
        sw2[tid] = (1.f-wx1)*wy1;
        sw3[tid] = wx1*wy1;
        float cx = px*128.f - 0.5f, cy = py*128.f - 0.5f;
        float cx0f = floorf(cx), cy0f = floorf(cy);
        int x0 = (int)cx0f, y0 = (int)cy0f;
        float cwx = cx - cx0f, cwy = cy - cy0f;
        float cs[NCLS];
        #pragma unroll
        for (int cc = 0; cc < NCLS; cc++) {
            const float* p = coarse + (size_t)(n*NCLS + cc)*CH*CH;
            float acc = 0.f;
            if (x0 >= 0   && y0 >= 0  ) acc += (1.f-cwx)*(1.f-cwy)*p[y0*CH + x0];
            if (x0+1 < CH && y0 >= 0  ) acc += cwx*(1.f-cwy)*p[y0*CH + x0+1];
            if (x0 >= 0   && y0+1 < CH) acc += (1.f-cwx)*cwy*p[(y0+1)*CH + x0];
            if (x0+1 < CH && y0+1 < CH) acc += cwx*cwy*p[(y0+1)*CH + x0+1];
            cs[cc] = acc;
        }
        int ad64 = xf_addr(tid, 64);
        int ad65 = xf_addr(tid, 65);
        float r0 = cs[0], r1 = cs[1], r2 = cs[2], r3 = 0.f;
        #pragma unroll
        for (int p = 0; p < NP; p++) {
            u32 pkA = pack_bf16x2(r0, r1);
            u32 pkB = pack_bf16x2(r2, r3);
            XP[p*PLU + ad64] = pkA;
            XP[p*PLU + ad65] = pkB;
            r0 -= bf16lo_f(pkA); r1 -= bf16hi_f(pkA);
            r2 -= bf16lo_f(pkB); r3 -= bf16hi_f(pkB);
        }
        #pragma unroll
        for (int c = 0; c < NCLS; c++)
            hsum[c*128 + tid] = __ldg(&wph[c*KIN + 128])*cs[0] + __ldg(&wph[c*KIN + 129])*cs[1]
                              + __ldg(&wph[c*KIN + 130])*cs[2] + __ldg(&bph[c]);
    }
    __syncthreads();

    const float* fbase = g_featT + (size_t)n*FH*FH*NIN;
    int ch0 = lane << 2;
    #pragma unroll 4
    for (int it = 0; it < 16; it++) {
        int pt = wrp + it*8;
        int x0 = sx0[pt], y0 = sy0[pt];
        bool xv0 = (x0 >= 0), xv1 = (x0+1 < FH), yv0 = (y0 >= 0), yv1 = (y0+1 < FH);
        float a0 = 0.f, a1 = 0.f, a2 = 0.f, a3 = 0.f;
        if (xv0 && yv0) { float w = sw0[pt]; float4 v = *(const float4*)(fbase + (size_t)((y0  )*FH + x0  )*NIN + ch0);
                          a0 += w*v.x; a1 += w*v.y; a2 += w*v.z; a3 += w*v.w; }
        if (xv1 && yv0) { float w = sw1[pt]; float4 v = *(const float4*)(fbase + (size_t)((y0  )*FH + x0+1)*NIN + ch0);
                          a0 += w*v.x; a1 += w*v.y; a2 += w*v.z; a3 += w*v.w; }
        if (xv0 && yv1) { float w = sw2[pt]; float4 v = *(const float4*)(fbase + (size_t)((y0+1)*FH + x0  )*NIN + ch0);
                          a0 += w*v.x; a1 += w*v.y; a2 += w*v.z; a3 += w*v.w; }
        if (xv1 && yv1) { float w = sw3[pt]; float4 v = *(const float4*)(fbase + (size_t)((y0+1)*FH + x0+1)*NIN + ch0);
                          a0 += w*v.x; a1 += w*v.y; a2 += w*v.z; a3 += w*v.w; }
        int ad0 = xf_addr(pt, (lane << 1));
        int ad1 = xf_addr(pt, (lane << 1) + 1);
        float r0 = a0, r1 = a1, r2 = a2, r3 = a3;
        #pragma unroll
        for (int p = 0; p < NP; p++) {
            u32 pkA = pack_bf16x2(r0, r1);
            u32 pkB = pack_bf16x2(r2, r3);
            XP[p*PLU + ad0] = pkA;
            XP[p*PLU + ad1] = pkB;
            r0 -= bf16lo_f(pkA); r1 -= bf16hi_f(pkA);
            r2 -= bf16lo_f(pkB); r3 -= bf16hi_f(pkB);
        }
    }
    __syncthreads();

    const int NPROD = (NP == 2) ? 3 : 6;
    const int PA[6] = {0, 0, 1, 1, 0, 2};
    const int PB[6] = {0, 1, 0, 1, 2, 0};

    int g = lane >> 2;
    int tig = lane & 3;
    int wm = wrp & 3;
    int wn = wrp >> 2;

    for (int l = 0; l < 3; l++) {
        const float* Bp = (l == 0) ? b1 : ((l == 1) ? b2 : b3);
        if (tid < 128) bias_s[tid] = __ldg(&Bp[tid]);
        __syncthreads();
        const u32* Wg = g_Wf + (size_t)l*3*PLU;

        float acc[2][8][4];
        #pragma unroll
        for (int mi = 0; mi < 2; mi++)
            #pragma unroll
            for (int j = 0; j < 8; j++) {
                acc[mi][j][0] = 0.f; acc[mi][j][1] = 0.f;
                acc[mi][j][2] = 0.f; acc[mi][j][3] = 0.f;
            }
        for (int ks = 0; ks < 9; ks++) {
            uint4 afA[NP], afB[NP];
            #pragma unroll
            for (int p = 0; p < NP; p++) {
                afA[p] = *(const uint4*)(XP + p*PLU + ((((2*wm  )*9 + ks)*32 + lane) << 2));
                afB[p] = *(const uint4*)(XP + p*PLU + ((((2*wm+1)*9 + ks)*32 + lane) << 2));
            }
            #pragma unroll
            for (int j = 0; j < 8; j++) {
                int nt = wn*8 + j;
                int boff = (((ks*16 + nt)*32 + lane) << 1);
                uint2 bfr[NP];
                #pragma unroll
                for (int p = 0; p < NP; p++)
                    bfr[p] = __ldg((const uint2*)(Wg + p*PLU + boff));
                #pragma unroll
                for (int q = 0; q < NPROD; q++) {
                    mma16816(acc[0][j], afA[PA[q]].x, afA[PA[q]].y, afA[PA[q]].z, afA[PA[q]].w,
                             bfr[PB[q]].x, bfr[PB[q]].y);
                    mma16816(acc[1][j], afB[PA[q]].x, afB[PA[q]].y, afB[PA[q]].z, afB[PA[q]].w,
                             bfr[PB[q]].x, bfr[PB[q]].y);
                }
            }
        }
        __syncthreads();

        #pragma unroll
        for (int mi = 0; mi < 2; mi++) {
            int mt = 2*wm + mi;
            #pragma unroll
            for (int j = 0; j < 8; j++) {
                int nt = wn*8 + j;
                int col = nt*8 + (tig << 1);
                float bA = bias_s[col], bB = bias_s[col + 1];
                float v0 = fmaxf(acc[mi][j][0] + bA, 0.f);
                float v1 = fmaxf(acc[mi][j][1] + bB, 0.f);
                float v2 = fmaxf(acc[mi][j][2] + bA, 0.f);
                float v3 = fmaxf(acc[mi][j][3] + bB, 0.f);
                int pi = nt*4 + tig;
                int adA = xf_addr(mt*16 + g, pi);
                float r0 = v0, r1 = v1, r2 = v2, r3 = v3;
                #pragma unroll
                for (int p = 0; p < NP; p++) {
                    u32 pkA = pack_bf16x2(r0, r1);
                    u32 pkB = pack_bf16x2(r2, r3);
                    *(uint2*)(XP + p*PLU + adA) = make_uint2(pkA, pkB);
                    r0 -= bf16lo_f(pkA); r1 -= bf16hi_f(pkA);
                    r2 -= bf16lo_f(pkB); r3 -= bf16hi_f(pkB);
                }
            }
        }
        __syncthreads();
    }

    if (tid < 128) {
        float s0 = 0.f, s1 = 0.f, s2 = 0.f;
        #pragma unroll 8
        for (int kp = 0; kp < 64; kp++) {
            int ad = xf_addr(tid, kp);
            float x0 = 0.f, x1 = 0.f;
            #pragma unroll
            for (int p = 0; p < NP; p++) {
                u32 v = XP[p*PLU + ad];
                x0 += bf16lo_f(v); x1 += bf16hi_f(v);
            }
            int k = kp << 1;
            s0 += __ldg(&wph[k])*x0 + __ldg(&wph[k+1])*x1;
            s1 += __ldg(&wph[KIN + k])*x0 + __ldg(&wph[KIN + k + 1])*x1;
            s2 += __ldg(&wph[2*KIN + k])*x0 + __ldg(&wph[2*KIN + k + 1])*x1;
        }
        int id = g_idx[pBase + tid];
        sem[(size_t)(n*NCLS + 0)*HW + id] = hsum[tid] + s0;
        sem[(size_t)(n*NCLS + 1)*HW + id] = hsum[128 + tid] + s1;
        sem[(size_t)(n*NCLS + 2)*HW + id] = hsum[256 + tid] + s2;
    }
}

// ---------------- launch ----------------
extern "C" void kernel_launch(void* const* d_in, const int* in_sizes, int n_in,
                              void* d_out, int out_size) {
    const float* coarse = (const float*)d_in[0];
    const float* feat   = (const float*)d_in[1];
    const float* w1 = (const float*)d_in[2];
    const float* b1 = (const float*)d_in[3];
    const float* w2 = (const float*)d_in[4];
    const float* b2 = (const float*)d_in[5];
    const float* w3 = (const float*)d_in[6];
    const float* b3 = (const float*)d_in[7];
    const float* wp = (const float*)d_in[8];
    const float* bp = (const float*)d_in[9];
    float* out = (float*)d_out;

    float* sem256;
    cudaGetSymbolAddress((void**)&sem256, g_sem256);

    static cudaStream_t sSide = nullptr;
    static cudaEvent_t evFork = nullptr, evJoin = nullptr;
    if (sSide == nullptr) {
        cudaStreamCreateWithFlags(&sSide, cudaStreamNonBlocking);
        cudaEventCreateWithFlags(&evFork, cudaEventDisableTiming);
        cudaEventCreateWithFlags(&evJoin, cudaEventDisableTiming);
    }

    const int SM3 = 3*PLB + 2048;   // 112,640 B -> 2 blocks/SM
    const int SM2 = 2*PLB + 2048;   //  75,776 B
    cudaFuncSetAttribute(mma_mlp<3>, cudaFuncAttributeMaxDynamicSharedMemorySize, SM3);
    cudaFuncSetAttribute(mma_mlp<2>, cudaFuncAttributeMaxDynamicSharedMemorySize, SM2);

    // side stream: W pack + feature transpose (independent of main-stream selection)
    cudaEventRecord(evFork, 0);
    cudaStreamWaitEvent(sSide, evFork, 0);
    wpack_kernel<<<128, 256, 0, sSide>>>(w1, w2, w3);
    transpose_kernel<<<dim3(2048, 4, 4), dim3(32, 8), 0, sSide>>>(feat);
    cudaEventRecord(evJoin, sSide);

    zero_kernel<<<64, 256>>>();

    for (int step = 0; step < 2; step++) {
        int logW = (step == 0) ? 8 : 9;
        int HW   = 1 << (2*logW);
        const float* semIn = (step == 0) ? coarse : sem256;
        float* semOut      = (step == 0) ? sem256 : out;

        upsample_sel<<<dim3(HW/1024, NB), 256>>>(semIn, semOut, logW);
        compact_sel<<<dim3(HW/2048, NB), 1024>>>(HW);

        if (step == 0) {
            cudaStreamWaitEvent(0, evJoin, 0);
            mma_mlp<3><<<PTOT/128, 256, SM3>>>(coarse, b1, b2, b3, wp, bp, semOut, HW, logW);
        } else {
            mma_mlp<2><<<PTOT/128, 256, SM2>>>(coarse, b1, b2, b3, wp, bp, semOut, HW, logW);
        }
    }
}